// round 4
// baseline (speedup 1.0000x reference)
#include <cuda_runtime.h>

#define NN 50000
#define NE 600000
#define CC 128
#define NG 64
#define EPSV 1e-5f
#define SBLK 200   // stats grid

// ---------------- scratch (device globals; no allocs allowed) ----------------
__device__ float g_h[NN * CC];     // GEMM output
__device__ float g_agg[NN * CC];   // aggregated messages (pre-BN)
__device__ int   g_degi[NN];
__device__ float g_dinv[NN];
__device__ int   g_src[NE];
__device__ int   g_dst[NE];
__device__ int   g_off[NN + 1];
__device__ int   g_cursor[NN];
__device__ int   g_bsum[256];
__device__ int   g_bsumx[256];
__device__ int2  g_edge[NE];       // CSR payload: {src, f32bits(weight)}
__device__ float g_psum[SBLK * CC];
__device__ float g_psq[SBLK * CC];
__device__ float g_scale[CC];
__device__ float g_shift[CC];
__device__ int   g_gstart[NG + 1];
__device__ int   g_is64;           // edge_index dtype flag
__device__ int   g_bis64;          // batch dtype flag (detected independently)

// ---------------- packed f32x2 helpers (sm_103a) ----------------
__device__ __forceinline__ unsigned long long bcast2(float x) {
    unsigned long long r;
    asm("mov.b64 %0, {%1, %1};" : "=l"(r) : "f"(x));
    return r;
}
__device__ __forceinline__ void fma2(unsigned long long& d,
                                     unsigned long long a,
                                     unsigned long long b) {
    asm("fma.rn.f32x2 %0, %1, %2, %0;" : "+l"(d) : "l"(a), "l"(b));
}
union U64F2 { unsigned long long u; float2 f; };

// ---------------- zero + dtype detection ----------------
// edge_index: values are random in [0, NN) -> int64 iff all interleaved high
// words are zero (prob of false positive ~ (1/NN)^16 ~ 0).
// batch: sorted, starts with many zeros, so the interleave test fails at the
// head. Use the tail: word [NN-1] is safe to read under either width (int32
// buffer has exactly NN words). int64 -> it's a high word (0) while word
// [NN-2] is the low word of element 24999 (mid graph id, nonzero w.h.p.);
// int32 -> it's batch[NN-1] ~ 63 (nonzero w.h.p.).
__global__ void zero_prep_kernel(const int* ei32, const int* b32) {
    int i = blockIdx.x * blockDim.x + threadIdx.x;
    if (i < NN) { g_degi[i] = 0; g_cursor[i] = 0; }
    if (blockIdx.x == 0 && threadIdx.x == 0) {
        int z = 1;
        #pragma unroll
        for (int k = 0; k < 16; k++)
            if (ei32[2 * k + 1] != 0) z = 0;
        g_is64 = z;
        g_bis64 = (b32[NN - 1] == 0 && b32[NN - 2] != 0) ? 1 : 0;
    }
}

__global__ void prep_kernel(const void* ei_raw) {
    int e = blockIdx.x * blockDim.x + threadIdx.x;
    if (e >= NE) return;
    int s, d;
    if (g_is64) {
        const long long* p = (const long long*)ei_raw;
        s = (int)p[e]; d = (int)p[NE + e];
    } else {
        const int* p = (const int*)ei_raw;
        s = p[e]; d = p[NE + e];
    }
    g_src[e] = s; g_dst[e] = d;
    atomicAdd(&g_degi[d], 1);
}

__global__ void dinv_kernel() {
    int i = blockIdx.x * blockDim.x + threadIdx.x;
    if (i >= NN) return;
    int d = g_degi[i];
    g_dinv[i] = (d > 0) ? rsqrtf((float)d) : 0.0f;
}

// ---------------- CSR build: exclusive scan of degrees + placement ----------
__global__ void scan1_kernel() {
    __shared__ int sh[256];
    int t = threadIdx.x;
    int i = blockIdx.x * 256 + t;
    int v = (i < NN) ? g_degi[i] : 0;
    sh[t] = v;
    __syncthreads();
    #pragma unroll
    for (int off = 1; off < 256; off <<= 1) {
        int tmp = (t >= off) ? sh[t - off] : 0;
        __syncthreads();
        sh[t] += tmp;
        __syncthreads();
    }
    if (i < NN) g_off[i] = sh[t] - v;      // exclusive within block
    if (t == 255) g_bsum[blockIdx.x] = sh[255];
}

__global__ void scan2_kernel(int nblocks) {
    __shared__ int sh[256];
    int t = threadIdx.x;
    int v = (t < nblocks) ? g_bsum[t] : 0;
    sh[t] = v;
    __syncthreads();
    #pragma unroll
    for (int off = 1; off < 256; off <<= 1) {
        int tmp = (t >= off) ? sh[t - off] : 0;
        __syncthreads();
        sh[t] += tmp;
        __syncthreads();
    }
    g_bsumx[t] = sh[t] - v;                // exclusive block offsets
}

__global__ void scan3_kernel() {
    int i = blockIdx.x * blockDim.x + threadIdx.x;
    if (i < NN) g_off[i] += g_bsumx[i >> 8];
    if (i == 0) g_off[NN] = NE;
}

// fill CSR slots; edge weight dinv[s]*dinv[d] computed inline
__global__ void fill_kernel() {
    int e = blockIdx.x * blockDim.x + threadIdx.x;
    if (e >= NE) return;
    int s = g_src[e];
    int d = g_dst[e];
    float w = g_dinv[s] * g_dinv[d];
    int p = atomicAdd(&g_cursor[d], 1);
    g_edge[g_off[d] + p] = make_int2(s, __float_as_int(w));
}

// ---------------- GEMM: [NN,128] @ [128,128] -> g_h ----------------
// fuse==1: A = relu(g_agg * g_scale + g_shift) applied inline on load (BN of
// the previous layer). fuse==0: A = Xext (raw input features).
__global__ void __launch_bounds__(256) gemm_kernel(const float* __restrict__ Xext,
                                                   const float* __restrict__ W,
                                                   int fuse) {
    const float* A = fuse ? (const float*)g_agg : Xext;
    __shared__ __align__(16) float Ws[16][128];
    __shared__ __align__(16) float As[16][132];  // 132*4=528B row stride (16B mult)
    int tid = threadIdx.x;
    int m0 = blockIdx.x * 128;
    int tx = tid & 15, ty = tid >> 4;

    unsigned long long acc2[8][4];
    #pragma unroll
    for (int i = 0; i < 8; i++)
        #pragma unroll
        for (int j = 0; j < 4; j++) acc2[i][j] = 0ULL;  // {+0.f, +0.f}

    for (int kk = 0; kk < 128; kk += 16) {
        // W chunk: 16 x 128, straight copy
        #pragma unroll
        for (int p = 0; p < 2; p++) {
            int f = tid * 2 + p;
            int k = f >> 5, n4 = f & 31;
            ((float4*)Ws[k])[n4] = ((const float4*)W)[(kk + k) * 32 + n4];
        }
        // A chunk: 128 rows x 16 cols, stored transposed As[k][row]
        #pragma unroll
        for (int p = 0; p < 2; p++) {
            int f = tid * 2 + p;
            int r = f >> 2, c4 = f & 3;
            int row = m0 + r;
            int col = kk + c4 * 4;
            float4 v = make_float4(0.f, 0.f, 0.f, 0.f);
            if (row < NN) v = *(const float4*)(A + row * CC + col);
            if (fuse) {
                float4 sc = *(const float4*)(g_scale + col);
                float4 sh = *(const float4*)(g_shift + col);
                v.x = fmaxf(fmaf(v.x, sc.x, sh.x), 0.f);
                v.y = fmaxf(fmaf(v.y, sc.y, sh.y), 0.f);
                v.z = fmaxf(fmaf(v.z, sc.z, sh.z), 0.f);
                v.w = fmaxf(fmaf(v.w, sc.w, sh.w), 0.f);
            }
            As[c4 * 4 + 0][r] = v.x;
            As[c4 * 4 + 1][r] = v.y;
            As[c4 * 4 + 2][r] = v.z;
            As[c4 * 4 + 3][r] = v.w;
        }
        __syncthreads();
        #pragma unroll
        for (int k = 0; k < 16; k++) {
            float a[8];
            unsigned long long bb[4];
            *(float4*)(a)     = *(float4*)&As[k][ty * 4];
            *(float4*)(a + 4) = *(float4*)&As[k][64 + ty * 4];
            {   // b operand as 64-bit column pairs, one LDS.128 each
                ulonglong2 t0 = *(ulonglong2*)&Ws[k][tx * 4];
                ulonglong2 t1 = *(ulonglong2*)&Ws[k][64 + tx * 4];
                bb[0] = t0.x; bb[1] = t0.y; bb[2] = t1.x; bb[3] = t1.y;
            }
            #pragma unroll
            for (int i = 0; i < 8; i++) {
                unsigned long long ai = bcast2(a[i]);
                fma2(acc2[i][0], ai, bb[0]);
                fma2(acc2[i][1], ai, bb[1]);
                fma2(acc2[i][2], ai, bb[2]);
                fma2(acc2[i][3], ai, bb[3]);
            }
        }
        __syncthreads();
    }
    #pragma unroll
    for (int i = 0; i < 8; i++) {
        int row = m0 + ((i < 4) ? (ty * 4 + i) : (64 + ty * 4 + (i - 4)));
        if (row < NN) {
            U64F2 p0, p1, p2, p3;
            p0.u = acc2[i][0]; p1.u = acc2[i][1];
            p2.u = acc2[i][2]; p3.u = acc2[i][3];
            float4 v0 = make_float4(p0.f.x, p0.f.y, p1.f.x, p1.f.y);
            float4 v1 = make_float4(p2.f.x, p2.f.y, p3.f.x, p3.f.y);
            *(float4*)(g_h + row * CC + tx * 4) = v0;
            *(float4*)(g_h + row * CC + 64 + tx * 4) = v1;
        }
    }
}

// ---------------- gather-style aggregation (no float atomics) ----------------
__global__ void __launch_bounds__(512) aggregate_kernel() {
    int node = blockIdx.x * 4 + (threadIdx.x >> 7);
    int c = threadIdx.x & 127;
    if (node >= NN) return;
    int s = g_off[node], e = g_off[node + 1];
    float a0 = 0.f, a1 = 0.f;
    int j = s;
    for (; j + 1 < e; j += 2) {
        int2 e0 = g_edge[j];
        int2 e1 = g_edge[j + 1];
        a0 += __int_as_float(e0.y) * g_h[e0.x * CC + c];
        a1 += __int_as_float(e1.y) * g_h[e1.x * CC + c];
    }
    if (j < e) {
        int2 e0 = g_edge[j];
        a0 += __int_as_float(e0.y) * g_h[e0.x * CC + c];
    }
    g_agg[node * CC + c] = a0 + a1;
}

// ---------------- BatchNorm stats (atomic-free partials) / finalize ----------
__global__ void __launch_bounds__(256) stats_kernel() {
    __shared__ float ssum[256];
    __shared__ float ssq[256];
    int c = threadIdx.x & 127;
    int sub = threadIdx.x >> 7;  // 0..1
    const int rpb = (NN + SBLK - 1) / SBLK;  // 250
    int r0 = blockIdx.x * rpb;
    int r1 = min(NN, r0 + rpb);
    float s = 0.f, s2 = 0.f;
    for (int r = r0 + sub; r < r1; r += 2) {
        float v = g_agg[r * CC + c];
        s += v; s2 += v * v;
    }
    ssum[threadIdx.x] = s;
    ssq[threadIdx.x] = s2;
    __syncthreads();
    if (threadIdx.x < 128) {
        g_psum[blockIdx.x * CC + c] = ssum[c] + ssum[c + 128];
        g_psq[blockIdx.x * CC + c]  = ssq[c] + ssq[c + 128];
    }
}

__global__ void finalize_kernel(const float* __restrict__ gam,
                                const float* __restrict__ bet) {
    int c = threadIdx.x;
    float s = 0.f, s2 = 0.f;
    for (int b = 0; b < SBLK; b++) {
        s  += g_psum[b * CC + c];
        s2 += g_psq[b * CC + c];
    }
    float mu = s * (1.0f / NN);
    float var = fmaxf(s2 * (1.0f / NN) - mu * mu, 0.f);
    float sc = gam[c] * rsqrtf(var + EPSV);
    g_scale[c] = sc;
    g_shift[c] = bet[c] - mu * sc;
}

// ---------------- graph boundaries (batch is sorted) + pool + head ----------
__global__ void bounds_kernel(const void* batch_raw) {
    int g = threadIdx.x;
    if (g > NG) return;
    int lo = 0, hi = NN;
    if (g_bis64) {
        const long long* b = (const long long*)batch_raw;
        while (lo < hi) { int mid = (lo + hi) >> 1; if (b[mid] < (long long)g) lo = mid + 1; else hi = mid; }
    } else {
        const int* b = (const int*)batch_raw;
        while (lo < hi) { int mid = (lo + hi) >> 1; if (b[mid] < g) lo = mid + 1; else hi = mid; }
    }
    g_gstart[g] = lo;
}

// Applies layer-3 BN+ReLU inline while pooling (reads pre-BN g_agg).
__global__ void pool_head_kernel(const float* __restrict__ Wh,
                                 const float* __restrict__ bh,
                                 float* __restrict__ out) {
    __shared__ float pooled[CC];
    int g = blockIdx.x;
    int c = threadIdx.x;
    int s = g_gstart[g], e = g_gstart[g + 1];
    float sc = g_scale[c], sh = g_shift[c];
    float a0 = 0.f, a1 = 0.f, a2 = 0.f, a3 = 0.f;
    int r = s;
    for (; r + 3 < e; r += 4) {
        a0 += fmaxf(fmaf(g_agg[(r + 0) * CC + c], sc, sh), 0.f);
        a1 += fmaxf(fmaf(g_agg[(r + 1) * CC + c], sc, sh), 0.f);
        a2 += fmaxf(fmaf(g_agg[(r + 2) * CC + c], sc, sh), 0.f);
        a3 += fmaxf(fmaf(g_agg[(r + 3) * CC + c], sc, sh), 0.f);
    }
    for (; r < e; r++) a0 += fmaxf(fmaf(g_agg[r * CC + c], sc, sh), 0.f);
    float cnt = (float)(e - s);
    pooled[c] = ((a0 + a1) + (a2 + a3)) / fmaxf(cnt, 1.0f);
    __syncthreads();
    if (c < 8) {
        float o = bh[c];
        #pragma unroll 8
        for (int k = 0; k < CC; k++) o += pooled[k] * Wh[k * 8 + c];
        out[g * 8 + c] = o;
    }
}

// ---------------- launch ----------------
extern "C" void kernel_launch(void* const* d_in, const int* in_sizes, int n_in,
                              void* d_out, int out_size) {
    const float* x  = (const float*)d_in[0];
    const void*  ei = d_in[1];
    const void*  batch = d_in[2];
    const float* W[3]  = { (const float*)d_in[3],  (const float*)d_in[7],  (const float*)d_in[11] };
    const float* gg[3] = { (const float*)d_in[5],  (const float*)d_in[9],  (const float*)d_in[13] };
    const float* be[3] = { (const float*)d_in[6],  (const float*)d_in[10], (const float*)d_in[14] };
    const float* Wh = (const float*)d_in[15];
    const float* bh = (const float*)d_in[16];
    float* out = (float*)d_out;

    const int EB = (NE + 255) / 256;   // 2344
    const int NB = (NN + 255) / 256;   // 196

    zero_prep_kernel<<<NB, 256>>>((const int*)ei, (const int*)batch);
    prep_kernel<<<EB, 256>>>(ei);
    dinv_kernel<<<NB, 256>>>();
    scan1_kernel<<<NB, 256>>>();
    scan2_kernel<<<1, 256>>>(NB);
    scan3_kernel<<<NB, 256>>>();
    fill_kernel<<<EB, 256>>>();

    for (int l = 0; l < 3; l++) {
        // layer l: GEMM (BN of layer l-1 fused into A-load for l>0)
        gemm_kernel<<<(NN + 127) / 128, 256>>>(x, W[l], l == 0 ? 0 : 1);
        aggregate_kernel<<<(NN + 3) / 4, 512>>>();
        stats_kernel<<<SBLK, 256>>>();
        finalize_kernel<<<1, 128>>>(gg[l], be[l]);
        // no apply pass: BN+ReLU consumed lazily by the next GEMM / pool
    }

    bounds_kernel<<<1, NG + 1>>>(batch);
    pool_head_kernel<<<NG, 128>>>(Wh, bh, out);
}

// round 5
// speedup vs baseline: 1.2496x; 1.2496x over previous
#include <cuda_runtime.h>
#include <cuda_bf16.h>

#define NN 50000
#define NE 600000
#define CC 128
#define NG 64
#define EPSV 1e-5f
#define SBLK 200   // stats grid

// ---------------- scratch (device globals; no allocs allowed) ----------------
__device__ unsigned int g_hb[NN * 64];   // GEMM output, bf16x2 packed (2 ch/uint)
__device__ float g_agg[NN * CC];         // aggregated messages (pre-BN), fp32
__device__ int   g_degi[NN];
__device__ float g_dinv[NN];
__device__ int   g_src[NE];
__device__ int   g_dst[NE];
__device__ int   g_off[NN + 1];
__device__ int   g_cursor[NN];
__device__ int   g_bsum[256];
__device__ int   g_bsumx[256];
__device__ int2  g_edge[NE];             // CSR payload: {src, f32bits(weight)}
__device__ float g_psum[SBLK * CC];
__device__ float g_psq[SBLK * CC];
__device__ float g_scale[CC];
__device__ float g_shift[CC];
__device__ int   g_is64;                 // edge_index dtype flag
__device__ int   g_bis64;                // batch dtype flag
__device__ int   g_cnt = 0;              // stats last-block counter

// ---------------- packed f32x2 helpers (sm_103a) ----------------
__device__ __forceinline__ unsigned long long bcast2(float x) {
    unsigned long long r;
    asm("mov.b64 %0, {%1, %1};" : "=l"(r) : "f"(x));
    return r;
}
__device__ __forceinline__ void fma2(unsigned long long& d,
                                     unsigned long long a,
                                     unsigned long long b) {
    asm("fma.rn.f32x2 %0, %1, %2, %0;" : "+l"(d) : "l"(a), "l"(b));
}
union U64F2 { unsigned long long u; float2 f; };

// ---------------- zero + dtype detection ----------------
// edge_index: random values in [0,NN) -> int64 iff all 16 sampled interleaved
// high words are zero. batch: sorted (head is all zeros, so use the tail):
// word [NN-1] readable under either width; int64 -> high word of elem 24999
// (0) while word [NN-2] = low word of elem 24999 (mid graph id, nonzero
// w.h.p.); int32 -> batch[NN-1] ~ 63 (nonzero w.h.p.).
__global__ void zero_prep_kernel(const int* ei32, const int* b32) {
    int i = blockIdx.x * blockDim.x + threadIdx.x;
    if (i < NN) { g_degi[i] = 0; g_cursor[i] = 0; }
    if (blockIdx.x == 0 && threadIdx.x == 0) {
        int z = 1;
        #pragma unroll
        for (int k = 0; k < 16; k++)
            if (ei32[2 * k + 1] != 0) z = 0;
        g_is64 = z;
        g_bis64 = (b32[NN - 1] == 0 && b32[NN - 2] != 0) ? 1 : 0;
    }
}

__global__ void prep_kernel(const void* ei_raw) {
    int e = blockIdx.x * blockDim.x + threadIdx.x;
    if (e >= NE) return;
    int s, d;
    if (g_is64) {
        const long long* p = (const long long*)ei_raw;
        s = (int)p[e]; d = (int)p[NE + e];
    } else {
        const int* p = (const int*)ei_raw;
        s = p[e]; d = p[NE + e];
    }
    g_src[e] = s; g_dst[e] = d;
    atomicAdd(&g_degi[d], 1);
}

// ---------------- CSR build: exclusive scan (dinv fused into scan1) --------
__global__ void scan1_kernel() {
    __shared__ int sh[256];
    int t = threadIdx.x;
    int i = blockIdx.x * 256 + t;
    int v = (i < NN) ? g_degi[i] : 0;
    if (i < NN) g_dinv[i] = (v > 0) ? rsqrtf((float)v) : 0.0f;
    sh[t] = v;
    __syncthreads();
    #pragma unroll
    for (int off = 1; off < 256; off <<= 1) {
        int tmp = (t >= off) ? sh[t - off] : 0;
        __syncthreads();
        sh[t] += tmp;
        __syncthreads();
    }
    if (i < NN) g_off[i] = sh[t] - v;      // exclusive within block
    if (t == 255) g_bsum[blockIdx.x] = sh[255];
}

__global__ void scan2_kernel(int nblocks) {
    __shared__ int sh[256];
    int t = threadIdx.x;
    int v = (t < nblocks) ? g_bsum[t] : 0;
    sh[t] = v;
    __syncthreads();
    #pragma unroll
    for (int off = 1; off < 256; off <<= 1) {
        int tmp = (t >= off) ? sh[t - off] : 0;
        __syncthreads();
        sh[t] += tmp;
        __syncthreads();
    }
    g_bsumx[t] = sh[t] - v;                // exclusive block offsets
}

__global__ void scan3_kernel() {
    int i = blockIdx.x * blockDim.x + threadIdx.x;
    if (i < NN) g_off[i] += g_bsumx[i >> 8];
    if (i == 0) g_off[NN] = NE;
}

// fill CSR slots; edge weight dinv[s]*dinv[d] computed inline
__global__ void fill_kernel() {
    int e = blockIdx.x * blockDim.x + threadIdx.x;
    if (e >= NE) return;
    int s = g_src[e];
    int d = g_dst[e];
    float w = g_dinv[s] * g_dinv[d];
    int p = atomicAdd(&g_cursor[d], 1);
    g_edge[g_off[d] + p] = make_int2(s, __float_as_int(w));
}

// ---------------- GEMM: [NN,128] @ [128,128] -> g_hb (bf16x2) ---------------
// fuse==1: A = relu(g_agg * g_scale + g_shift) applied inline on load (BN of
// the previous layer). fuse==0: A = Xext (raw input features).
__global__ void __launch_bounds__(256) gemm_kernel(const float* __restrict__ Xext,
                                                   const float* __restrict__ W,
                                                   int fuse) {
    const float* A = fuse ? (const float*)g_agg : Xext;
    __shared__ __align__(16) float Ws[16][128];
    __shared__ __align__(16) float As[16][132];  // 528B row stride (16B mult)
    int tid = threadIdx.x;
    int m0 = blockIdx.x * 128;
    int tx = tid & 15, ty = tid >> 4;

    unsigned long long acc2[8][4];
    #pragma unroll
    for (int i = 0; i < 8; i++)
        #pragma unroll
        for (int j = 0; j < 4; j++) acc2[i][j] = 0ULL;  // {+0.f, +0.f}

    for (int kk = 0; kk < 128; kk += 16) {
        #pragma unroll
        for (int p = 0; p < 2; p++) {
            int f = tid * 2 + p;
            int k = f >> 5, n4 = f & 31;
            ((float4*)Ws[k])[n4] = ((const float4*)W)[(kk + k) * 32 + n4];
        }
        #pragma unroll
        for (int p = 0; p < 2; p++) {
            int f = tid * 2 + p;
            int r = f >> 2, c4 = f & 3;
            int row = m0 + r;
            int col = kk + c4 * 4;
            float4 v = make_float4(0.f, 0.f, 0.f, 0.f);
            if (row < NN) v = *(const float4*)(A + row * CC + col);
            if (fuse) {
                float4 sc = *(const float4*)(g_scale + col);
                float4 sh = *(const float4*)(g_shift + col);
                v.x = fmaxf(fmaf(v.x, sc.x, sh.x), 0.f);
                v.y = fmaxf(fmaf(v.y, sc.y, sh.y), 0.f);
                v.z = fmaxf(fmaf(v.z, sc.z, sh.z), 0.f);
                v.w = fmaxf(fmaf(v.w, sc.w, sh.w), 0.f);
            }
            As[c4 * 4 + 0][r] = v.x;
            As[c4 * 4 + 1][r] = v.y;
            As[c4 * 4 + 2][r] = v.z;
            As[c4 * 4 + 3][r] = v.w;
        }
        __syncthreads();
        #pragma unroll
        for (int k = 0; k < 16; k++) {
            float a[8];
            unsigned long long bb[4];
            *(float4*)(a)     = *(float4*)&As[k][ty * 4];
            *(float4*)(a + 4) = *(float4*)&As[k][64 + ty * 4];
            {   // b operand as 64-bit column pairs, one LDS.128 each
                ulonglong2 t0 = *(ulonglong2*)&Ws[k][tx * 4];
                ulonglong2 t1 = *(ulonglong2*)&Ws[k][64 + tx * 4];
                bb[0] = t0.x; bb[1] = t0.y; bb[2] = t1.x; bb[3] = t1.y;
            }
            #pragma unroll
            for (int i = 0; i < 8; i++) {
                unsigned long long ai = bcast2(a[i]);
                fma2(acc2[i][0], ai, bb[0]);
                fma2(acc2[i][1], ai, bb[1]);
                fma2(acc2[i][2], ai, bb[2]);
                fma2(acc2[i][3], ai, bb[3]);
            }
        }
        __syncthreads();
    }
    // epilogue: convert to bf16x2 and store (h consumed only by the gather)
    #pragma unroll
    for (int i = 0; i < 8; i++) {
        int row = m0 + ((i < 4) ? (ty * 4 + i) : (64 + ty * 4 + (i - 4)));
        if (row < NN) {
            U64F2 p0, p1, p2, p3;
            p0.u = acc2[i][0]; p1.u = acc2[i][1];
            p2.u = acc2[i][2]; p3.u = acc2[i][3];
            __nv_bfloat162 b0 = __floats2bfloat162_rn(p0.f.x, p0.f.y);
            __nv_bfloat162 b1 = __floats2bfloat162_rn(p1.f.x, p1.f.y);
            __nv_bfloat162 b2 = __floats2bfloat162_rn(p2.f.x, p2.f.y);
            __nv_bfloat162 b3 = __floats2bfloat162_rn(p3.f.x, p3.f.y);
            unsigned int u0 = *(unsigned int*)&b0;
            unsigned int u1 = *(unsigned int*)&b1;
            unsigned int u2 = *(unsigned int*)&b2;
            unsigned int u3 = *(unsigned int*)&b3;
            *(uint2*)(g_hb + row * 64 + tx * 2)      = make_uint2(u0, u1);
            *(uint2*)(g_hb + row * 64 + 32 + tx * 2) = make_uint2(u2, u3);
        }
    }
}

// ---------------- gather-style aggregation (bf16 rows, no float atomics) ----
// 64 threads per node, 2 channels each (bf16x2 load); 8 nodes / 512-thr block.
__global__ void __launch_bounds__(512) aggregate_kernel() {
    int node = blockIdx.x * 8 + (threadIdx.x >> 6);
    int c = threadIdx.x & 63;
    if (node >= NN) return;
    int s = g_off[node], e = g_off[node + 1];
    float ax0 = 0.f, ay0 = 0.f, ax1 = 0.f, ay1 = 0.f;
    int j = s;
    for (; j + 1 < e; j += 2) {
        int2 e0 = g_edge[j];
        int2 e1 = g_edge[j + 1];
        unsigned int u0 = g_hb[e0.x * 64 + c];
        unsigned int u1 = g_hb[e1.x * 64 + c];
        float2 f0 = __bfloat1622float2(*(__nv_bfloat162*)&u0);
        float2 f1 = __bfloat1622float2(*(__nv_bfloat162*)&u1);
        float w0 = __int_as_float(e0.y);
        float w1 = __int_as_float(e1.y);
        ax0 += w0 * f0.x; ay0 += w0 * f0.y;
        ax1 += w1 * f1.x; ay1 += w1 * f1.y;
    }
    if (j < e) {
        int2 e0 = g_edge[j];
        unsigned int u0 = g_hb[e0.x * 64 + c];
        float2 f0 = __bfloat1622float2(*(__nv_bfloat162*)&u0);
        float w0 = __int_as_float(e0.y);
        ax0 += w0 * f0.x; ay0 += w0 * f0.y;
    }
    *(float2*)(g_agg + node * CC + 2 * c) = make_float2(ax0 + ax1, ay0 + ay1);
}

// ---------------- BN stats with fused last-block finalize -------------------
__global__ void __launch_bounds__(256) stats_kernel(const float* __restrict__ gam,
                                                    const float* __restrict__ bet) {
    __shared__ float ssum[256];
    __shared__ float ssq[256];
    __shared__ int slast;
    int c = threadIdx.x & 127;
    int sub = threadIdx.x >> 7;  // 0..1
    const int rpb = (NN + SBLK - 1) / SBLK;  // 250
    int r0 = blockIdx.x * rpb;
    int r1 = min(NN, r0 + rpb);
    float s = 0.f, s2 = 0.f;
    for (int r = r0 + sub; r < r1; r += 2) {
        float v = g_agg[r * CC + c];
        s += v; s2 += v * v;
    }
    ssum[threadIdx.x] = s;
    ssq[threadIdx.x] = s2;
    __syncthreads();
    if (threadIdx.x < 128) {
        g_psum[blockIdx.x * CC + c] = ssum[c] + ssum[c + 128];
        g_psq[blockIdx.x * CC + c]  = ssq[c] + ssq[c + 128];
    }
    // last-arriving block finalizes scale/shift (saves a launch)
    __threadfence();
    if (threadIdx.x == 0)
        slast = (atomicAdd(&g_cnt, 1) == SBLK - 1) ? 1 : 0;
    __syncthreads();
    if (slast) {
        __threadfence();  // acquire: see all blocks' partials
        if (threadIdx.x < 128) {
            float ts = 0.f, ts2 = 0.f;
            for (int b = 0; b < SBLK; b++) {
                ts  += g_psum[b * CC + threadIdx.x];
                ts2 += g_psq[b * CC + threadIdx.x];
            }
            float mu = ts * (1.0f / NN);
            float var = fmaxf(ts2 * (1.0f / NN) - mu * mu, 0.f);
            float sc = gam[threadIdx.x] * rsqrtf(var + EPSV);
            g_scale[threadIdx.x] = sc;
            g_shift[threadIdx.x] = bet[threadIdx.x] - mu * sc;
        }
        __syncthreads();
        if (threadIdx.x == 0) g_cnt = 0;  // reset for next layer / replay
    }
}

// ---------------- pool + head (bounds search inlined; layer-3 BN fused) -----
__global__ void pool_head_kernel(const void* batch_raw,
                                 const float* __restrict__ Wh,
                                 const float* __restrict__ bh,
                                 float* __restrict__ out) {
    __shared__ float pooled[CC];
    __shared__ int sb[2];
    int g = blockIdx.x;
    int c = threadIdx.x;
    if (c < 2) {
        int target = g + c;
        int lo = 0, hi = NN;
        if (g_bis64) {
            const long long* b = (const long long*)batch_raw;
            while (lo < hi) { int mid = (lo + hi) >> 1; if (b[mid] < (long long)target) lo = mid + 1; else hi = mid; }
        } else {
            const int* b = (const int*)batch_raw;
            while (lo < hi) { int mid = (lo + hi) >> 1; if (b[mid] < target) lo = mid + 1; else hi = mid; }
        }
        sb[c] = lo;
    }
    __syncthreads();
    int s = sb[0], e = sb[1];
    float sc = g_scale[c], sh = g_shift[c];
    float a0 = 0.f, a1 = 0.f, a2 = 0.f, a3 = 0.f;
    int r = s;
    for (; r + 3 < e; r += 4) {
        a0 += fmaxf(fmaf(g_agg[(r + 0) * CC + c], sc, sh), 0.f);
        a1 += fmaxf(fmaf(g_agg[(r + 1) * CC + c], sc, sh), 0.f);
        a2 += fmaxf(fmaf(g_agg[(r + 2) * CC + c], sc, sh), 0.f);
        a3 += fmaxf(fmaf(g_agg[(r + 3) * CC + c], sc, sh), 0.f);
    }
    for (; r < e; r++) a0 += fmaxf(fmaf(g_agg[r * CC + c], sc, sh), 0.f);
    float cnt = (float)(e - s);
    pooled[c] = ((a0 + a1) + (a2 + a3)) / fmaxf(cnt, 1.0f);
    __syncthreads();
    if (c < 8) {
        float o = bh[c];
        #pragma unroll 8
        for (int k = 0; k < CC; k++) o += pooled[k] * Wh[k * 8 + c];
        out[g * 8 + c] = o;
    }
}

// ---------------- launch ----------------
extern "C" void kernel_launch(void* const* d_in, const int* in_sizes, int n_in,
                              void* d_out, int out_size) {
    const float* x  = (const float*)d_in[0];
    const void*  ei = d_in[1];
    const void*  batch = d_in[2];
    const float* W[3]  = { (const float*)d_in[3],  (const float*)d_in[7],  (const float*)d_in[11] };
    const float* gg[3] = { (const float*)d_in[5],  (const float*)d_in[9],  (const float*)d_in[13] };
    const float* be[3] = { (const float*)d_in[6],  (const float*)d_in[10], (const float*)d_in[14] };
    const float* Wh = (const float*)d_in[15];
    const float* bh = (const float*)d_in[16];
    float* out = (float*)d_out;

    const int EB = (NE + 255) / 256;   // 2344
    const int NB = (NN + 255) / 256;   // 196

    zero_prep_kernel<<<NB, 256>>>((const int*)ei, (const int*)batch);
    prep_kernel<<<EB, 256>>>(ei);
    scan1_kernel<<<NB, 256>>>();
    scan2_kernel<<<1, 256>>>(NB);
    scan3_kernel<<<NB, 256>>>();
    fill_kernel<<<EB, 256>>>();

    for (int l = 0; l < 3; l++) {
        gemm_kernel<<<(NN + 127) / 128, 256>>>(x, W[l], l == 0 ? 0 : 1);
        aggregate_kernel<<<NN / 8, 512>>>();
        stats_kernel<<<SBLK, 256>>>(gg[l], be[l]);
    }

    pool_head_kernel<<<NG, 128>>>(batch, Wh, bh, out);
}